// round 4
// baseline (speedup 1.0000x reference)
#include <cuda_runtime.h>
#include <math.h>

// Problem constants (fixed by the reference)
#define BSZ   16
#define MDIM  1024
#define NDIM  1024
#define DTDIM 1024
#define HIDD  512
#define NEGINF (-1.0e9f)

static const long long SLAB = (long long)BSZ * MDIM * NDIM;  // 16,777,216 elems

// Scratch: 4 slabs of (B, 1024, 1024) fp32 = 256 MB, reused across phases.
__device__ float g_scratch[4ULL * BSZ * MDIM * NDIM];
__device__ float g_pool[BSZ * 2 * DTDIM];
__device__ float g_l[BSZ];

// ---------------------------------------------------------------------------
// Pool: g_pool[b][0:1024] = mean_m oV[b,m,:],  g_pool[b][1024:2048] = mean_n oT
// ---------------------------------------------------------------------------
__global__ void pool_kernel(const float* __restrict__ oV, const float* __restrict__ oT) {
    int b = blockIdx.x;
    int which = blockIdx.y;  // 0 = V, 1 = T
    const float* src = (which == 0 ? oV : oT) + (long long)b * MDIM * DTDIM;
    for (int d = threadIdx.x; d < DTDIM; d += blockDim.x) {
        float s = 0.f;
        for (int m = 0; m < MDIM; m++) s += src[(long long)m * DTDIM + d];
        g_pool[b * 2 * DTDIM + which * DTDIM + d] = s * (1.0f / MDIM);
    }
}

// ---------------------------------------------------------------------------
// FFN: h = relu(pool @ W1^T + b1); l = sigmoid(h @ W2^T + b2)
// One block (512 threads) per batch.
// ---------------------------------------------------------------------------
__global__ void ffn_kernel(const float* __restrict__ w1, const float* __restrict__ b1,
                           const float* __restrict__ w2, const float* __restrict__ b2) {
    int b = blockIdx.x;
    __shared__ float sp[2 * DTDIM];
    __shared__ float red[HIDD];
    for (int i = threadIdx.x; i < 2 * DTDIM; i += blockDim.x)
        sp[i] = g_pool[b * 2 * DTDIM + i];
    __syncthreads();
    int j = threadIdx.x;  // 0..511
    float acc = b1[j];
    const float* wrow = w1 + (long long)j * (2 * DTDIM);
    #pragma unroll 8
    for (int i = 0; i < 2 * DTDIM; i++) acc += wrow[i] * sp[i];
    float h = acc > 0.f ? acc : 0.f;
    red[j] = h * w2[j];
    __syncthreads();
    for (int s = HIDD / 2; s > 0; s >>= 1) {
        if (j < s) red[j] += red[j + s];
        __syncthreads();
    }
    if (j == 0) g_l[b] = 1.0f / (1.0f + expf(-(red[0] + b2[0])));
}

// ---------------------------------------------------------------------------
// SGEMM: C[m,n] = sum_k A[m,k] * Bop[k,n] (+ bias[n])
//   BT=true : B row-major (N x K), contract over last dim  (C = A @ B^T)
//   BT=false: B row-major (K x N)                          (C = A @ B)
// 128x128 block tile, BK=16, 256 threads, 8x8 microtile. Dims must be
// multiples of 128 / 16 (they are: 1024).
// ---------------------------------------------------------------------------
template <bool BT, bool HASBIAS>
__global__ __launch_bounds__(256, 2)
void gemm128(const float* __restrict__ A, long long sA,
             const float* __restrict__ B, long long sB,
             float* __restrict__ C, long long sC,
             const float* __restrict__ bias,
             int M, int N, int K) {
    __shared__ float As[16][128];
    __shared__ float Bs[16][128];

    int bz = blockIdx.z;
    A += (long long)bz * sA;
    B += (long long)bz * sB;
    C += (long long)bz * sC;

    const int m0 = blockIdx.y * 128;
    const int n0 = blockIdx.x * 128;
    const int tid = threadIdx.x;
    const int tx = tid % 16;   // n direction
    const int ty = tid / 16;   // m direction

    // Transposed-tile load mapping (A always; B when BT)
    const int aRow = tid / 4;          // 0..63 (+64)
    const int aCol = (tid % 4) * 4;    // 0,4,8,12
    // Direct-tile load mapping (B when !BT)
    const int bRow = tid / 32;         // 0..7 (+8)
    const int bCol = (tid % 32) * 4;   // 0..124

    float acc[8][8];
    #pragma unroll
    for (int i = 0; i < 8; i++)
        #pragma unroll
        for (int j = 0; j < 8; j++) acc[i][j] = 0.f;

    for (int k0 = 0; k0 < K; k0 += 16) {
        #pragma unroll
        for (int h = 0; h < 2; h++) {
            int r = aRow + h * 64;
            float4 v = *reinterpret_cast<const float4*>(
                &A[(long long)(m0 + r) * K + k0 + aCol]);
            As[aCol + 0][r] = v.x; As[aCol + 1][r] = v.y;
            As[aCol + 2][r] = v.z; As[aCol + 3][r] = v.w;
        }
        if (BT) {
            #pragma unroll
            for (int h = 0; h < 2; h++) {
                int r = aRow + h * 64;
                float4 v = *reinterpret_cast<const float4*>(
                    &B[(long long)(n0 + r) * K + k0 + aCol]);
                Bs[aCol + 0][r] = v.x; Bs[aCol + 1][r] = v.y;
                Bs[aCol + 2][r] = v.z; Bs[aCol + 3][r] = v.w;
            }
        } else {
            #pragma unroll
            for (int h = 0; h < 2; h++) {
                int r = bRow + h * 8;
                float4 v = *reinterpret_cast<const float4*>(
                    &B[(long long)(k0 + r) * N + n0 + bCol]);
                *reinterpret_cast<float4*>(&Bs[r][bCol]) = v;
            }
        }
        __syncthreads();

        #pragma unroll
        for (int kk = 0; kk < 16; kk++) {
            float ra[8], rb[8];
            #pragma unroll
            for (int i = 0; i < 8; i++) ra[i] = As[kk][ty * 8 + i];
            #pragma unroll
            for (int j = 0; j < 8; j++) rb[j] = Bs[kk][tx * 8 + j];
            #pragma unroll
            for (int i = 0; i < 8; i++)
                #pragma unroll
                for (int j = 0; j < 8; j++) acc[i][j] += ra[i] * rb[j];
        }
        __syncthreads();
    }

    #pragma unroll
    for (int i = 0; i < 8; i++) {
        int m = m0 + ty * 8 + i;
        #pragma unroll
        for (int j = 0; j < 8; j += 4) {
            int n = n0 + tx * 8 + j;
            float4 v;
            v.x = acc[i][j];     v.y = acc[i][j + 1];
            v.z = acc[i][j + 2]; v.w = acc[i][j + 3];
            if (HASBIAS) {
                v.x += bias[n];     v.y += bias[n + 1];
                v.z += bias[n + 2]; v.w += bias[n + 3];
            }
            *reinterpret_cast<float4*>(&C[(long long)m * N + n]) = v;
        }
    }
}

// ---------------------------------------------------------------------------
// softmax(sim * inv_sqrt) row-wise, threshold against l[b], write mask (0/1)
// One block (256 threads) per row of 1024.
// ---------------------------------------------------------------------------
__global__ void softmax_mask_kernel(const float* __restrict__ sim,
                                    float* __restrict__ mask) {
    const int row = blockIdx.x;       // b*M + m
    const int b = row >> 10;
    const float inv = 0.03125f;       // 1/sqrt(1024)
    __shared__ float srow[NDIM];
    __shared__ float red[256];
    const float* p = sim + (long long)row * NDIM;

    float lm = -1e30f;
    for (int j = threadIdx.x; j < NDIM; j += 256) {
        float v = p[j] * inv;
        srow[j] = v;
        lm = fmaxf(lm, v);
    }
    red[threadIdx.x] = lm;
    __syncthreads();
    for (int s = 128; s > 0; s >>= 1) {
        if (threadIdx.x < s) red[threadIdx.x] = fmaxf(red[threadIdx.x], red[threadIdx.x + s]);
        __syncthreads();
    }
    float mx = red[0];
    __syncthreads();

    float ls = 0.f;
    for (int j = threadIdx.x; j < NDIM; j += 256) ls += expf(srow[j] - mx);
    red[threadIdx.x] = ls;
    __syncthreads();
    for (int s = 128; s > 0; s >>= 1) {
        if (threadIdx.x < s) red[threadIdx.x] += red[threadIdx.x + s];
        __syncthreads();
    }
    float sum = red[0];
    float thr = g_l[b] * sum;   // S >= l  <=>  exp(x-mx) >= l*sum

    float* mrow = mask + (long long)row * NDIM;
    for (int j = threadIdx.x; j < NDIM; j += 256)
        mrow[j] = (expf(srow[j] - mx) >= thr) ? 1.f : 0.f;
}

// ---------------------------------------------------------------------------
// Masked softmax in place: p = softmax(where(mask, p*inv, -1e9)) per row.
// TRANS=false: mask[b][i][j]; TRANS=true: mask[b][j][i] (transposed mask).
// ---------------------------------------------------------------------------
template <bool TRANS>
__global__ void masked_softmax_kernel(float* __restrict__ scores,
                                      const float* __restrict__ mask) {
    const int row = blockIdx.x;    // b*1024 + i
    const int b = row >> 10;
    const int i = row & 1023;
    const float inv = 0.03125f;
    __shared__ float srow[NDIM];
    __shared__ float red[256];
    float* p = scores + (long long)row * NDIM;
    const float* mbase = mask + (long long)b * MDIM * NDIM;

    float lm = -1e30f;
    for (int j = threadIdx.x; j < NDIM; j += 256) {
        float mval = TRANS ? mbase[(long long)j * NDIM + i]
                           : mbase[(long long)i * NDIM + j];
        float v = (mval != 0.f) ? p[j] * inv : NEGINF;
        srow[j] = v;
        lm = fmaxf(lm, v);
    }
    red[threadIdx.x] = lm;
    __syncthreads();
    for (int s = 128; s > 0; s >>= 1) {
        if (threadIdx.x < s) red[threadIdx.x] = fmaxf(red[threadIdx.x], red[threadIdx.x + s]);
        __syncthreads();
    }
    float mx = red[0];
    __syncthreads();

    float ls = 0.f;
    for (int j = threadIdx.x; j < NDIM; j += 256) ls += expf(srow[j] - mx);
    red[threadIdx.x] = ls;
    __syncthreads();
    for (int s = 128; s > 0; s >>= 1) {
        if (threadIdx.x < s) red[threadIdx.x] += red[threadIdx.x + s];
        __syncthreads();
    }
    float rsum = 1.0f / red[0];

    for (int j = threadIdx.x; j < NDIM; j += 256)
        p[j] = expf(srow[j] - mx) * rsum;
}

// ---------------------------------------------------------------------------
// Launch
// ---------------------------------------------------------------------------
extern "C" void kernel_launch(void* const* d_in, const int* in_sizes, int n_in,
                              void* d_out, int out_size) {
    const float* oV     = (const float*)d_in[0];
    const float* oT     = (const float*)d_in[1];
    const float* Wq_v_w = (const float*)d_in[2];
    const float* Wq_v_b = (const float*)d_in[3];
    const float* Wk_t_w = (const float*)d_in[4];
    const float* Wk_t_b = (const float*)d_in[5];
    const float* Wv_t_w = (const float*)d_in[6];
    const float* Wv_t_b = (const float*)d_in[7];
    const float* Wq_t_w = (const float*)d_in[8];
    const float* Wq_t_b = (const float*)d_in[9];
    const float* Wk_v_w = (const float*)d_in[10];
    const float* Wk_v_b = (const float*)d_in[11];
    const float* Wv_v_w = (const float*)d_in[12];
    const float* Wv_v_b = (const float*)d_in[13];
    const float* ffn1_w = (const float*)d_in[14];
    const float* ffn1_b = (const float*)d_in[15];
    const float* ffn2_w = (const float*)d_in[16];
    const float* ffn2_b = (const float*)d_in[17];

    float* out = (float*)d_out;
    float* out_vt  = out;
    float* out_tv  = out + (long long)BSZ * MDIM * DTDIM;
    float* maskout = out + 2LL * BSZ * MDIM * DTDIM;

    float* scr = nullptr;
    cudaGetSymbolAddress((void**)&scr, g_scratch);
    float* s0 = scr;             // sim / scores
    float* s1 = scr + SLAB;      // Q
    float* s2 = scr + 2 * SLAB;  // K
    float* s3 = scr + 3 * SLAB;  // V

    const long long S = (long long)MDIM * NDIM;  // per-batch stride (all 1024x1024)
    dim3 ggrid(NDIM / 128, MDIM / 128, BSZ);

    // Phase 0: pooled FFN threshold
    pool_kernel<<<dim3(BSZ, 2), 256>>>(oV, oT);
    ffn_kernel<<<BSZ, HIDD>>>(ffn1_w, ffn1_b, ffn2_w, ffn2_b);

    // Phase 1: sim = oV @ oT^T, softmax+threshold -> mask
    gemm128<true, false><<<ggrid, 256>>>(oV, S, oT, S, s0, S, nullptr, MDIM, NDIM, DTDIM);
    softmax_mask_kernel<<<BSZ * MDIM, 256>>>(s0, maskout);

    // Phase 2: V -> T attention
    gemm128<true, true><<<ggrid, 256>>>(oV, S, Wq_v_w, 0, s1, S, Wq_v_b, MDIM, DTDIM, DTDIM);
    gemm128<true, true><<<ggrid, 256>>>(oT, S, Wk_t_w, 0, s2, S, Wk_t_b, NDIM, DTDIM, DTDIM);
    gemm128<true, true><<<ggrid, 256>>>(oT, S, Wv_t_w, 0, s3, S, Wv_t_b, NDIM, DTDIM, DTDIM);
    gemm128<true, false><<<ggrid, 256>>>(s1, S, s2, S, s0, S, nullptr, MDIM, NDIM, DTDIM);
    masked_softmax_kernel<false><<<BSZ * MDIM, 256>>>(s0, maskout);
    gemm128<false, false><<<ggrid, 256>>>(s0, S, s3, S, out_vt, S, nullptr, MDIM, DTDIM, NDIM);

    // Phase 3: T -> V attention (transposed mask)
    gemm128<true, true><<<ggrid, 256>>>(oT, S, Wq_t_w, 0, s1, S, Wq_t_b, NDIM, DTDIM, DTDIM);
    gemm128<true, true><<<ggrid, 256>>>(oV, S, Wk_v_w, 0, s2, S, Wk_v_b, MDIM, DTDIM, DTDIM);
    gemm128<true, true><<<ggrid, 256>>>(oV, S, Wv_v_w, 0, s3, S, Wv_v_b, MDIM, DTDIM, DTDIM);
    gemm128<true, false><<<ggrid, 256>>>(s1, S, s2, S, s0, S, nullptr, NDIM, MDIM, DTDIM);
    masked_softmax_kernel<true><<<BSZ * NDIM, 256>>>(s0, maskout);
    gemm128<false, false><<<ggrid, 256>>>(s0, S, s3, S, out_tv, S, nullptr, NDIM, DTDIM, MDIM);
}

// round 5
// speedup vs baseline: 1.0004x; 1.0004x over previous
#include <cuda_runtime.h>
#include <math.h>

// Problem constants (fixed by the reference)
#define BSZ   16
#define MDIM  1024
#define NDIM  1024
#define DTDIM 1024
#define HIDD  512
#define NEGINF (-1.0e9f)

static const long long SLAB = (long long)BSZ * MDIM * NDIM;  // 16,777,216 elems

// Scratch: 4 slabs of (B, 1024, 1024) fp32 = 256 MB, reused across phases.
__device__ float g_scratch[4ULL * BSZ * MDIM * NDIM];
__device__ float g_pool[BSZ * 2 * DTDIM];
__device__ float g_l[BSZ];

// ---------------------------------------------------------------------------
// Pool: g_pool[b][0:1024] = mean_m oV[b,m,:],  g_pool[b][1024:2048] = mean_n oT
// ---------------------------------------------------------------------------
__global__ void pool_kernel(const float* __restrict__ oV, const float* __restrict__ oT) {
    int b = blockIdx.x;
    int which = blockIdx.y;  // 0 = V, 1 = T
    const float* src = (which == 0 ? oV : oT) + (long long)b * MDIM * DTDIM;
    for (int d = threadIdx.x; d < DTDIM; d += blockDim.x) {
        float s = 0.f;
        for (int m = 0; m < MDIM; m++) s += src[(long long)m * DTDIM + d];
        g_pool[b * 2 * DTDIM + which * DTDIM + d] = s * (1.0f / MDIM);
    }
}

// ---------------------------------------------------------------------------
// FFN: h = relu(pool @ W1^T + b1); l = sigmoid(h @ W2^T + b2)
// One block (512 threads) per batch.
// ---------------------------------------------------------------------------
__global__ void ffn_kernel(const float* __restrict__ w1, const float* __restrict__ b1,
                           const float* __restrict__ w2, const float* __restrict__ b2) {
    int b = blockIdx.x;
    __shared__ float sp[2 * DTDIM];
    __shared__ float red[HIDD];
    for (int i = threadIdx.x; i < 2 * DTDIM; i += blockDim.x)
        sp[i] = g_pool[b * 2 * DTDIM + i];
    __syncthreads();
    int j = threadIdx.x;  // 0..511
    float acc = b1[j];
    const float* wrow = w1 + (long long)j * (2 * DTDIM);
    #pragma unroll 8
    for (int i = 0; i < 2 * DTDIM; i++) acc += wrow[i] * sp[i];
    float h = acc > 0.f ? acc : 0.f;
    red[j] = h * w2[j];
    __syncthreads();
    for (int s = HIDD / 2; s > 0; s >>= 1) {
        if (j < s) red[j] += red[j + s];
        __syncthreads();
    }
    if (j == 0) g_l[b] = 1.0f / (1.0f + expf(-(red[0] + b2[0])));
}

// ---------------------------------------------------------------------------
// SGEMM: C[m,n] = sum_k A[m,k] * Bop[k,n] (+ bias[n])
//   BT=true : B row-major (N x K), contract over last dim  (C = A @ B^T)
//   BT=false: B row-major (K x N)                          (C = A @ B)
// 128x128 block tile, BK=16, 256 threads, 8x8 microtile. Dims must be
// multiples of 128 / 16 (they are: 1024).
// ---------------------------------------------------------------------------
template <bool BT, bool HASBIAS>
__global__ __launch_bounds__(256, 2)
void gemm128(const float* __restrict__ A, long long sA,
             const float* __restrict__ B, long long sB,
             float* __restrict__ C, long long sC,
             const float* __restrict__ bias,
             int M, int N, int K) {
    __shared__ float As[16][128];
    __shared__ float Bs[16][128];

    int bz = blockIdx.z;
    A += (long long)bz * sA;
    B += (long long)bz * sB;
    C += (long long)bz * sC;

    const int m0 = blockIdx.y * 128;
    const int n0 = blockIdx.x * 128;
    const int tid = threadIdx.x;
    const int tx = tid % 16;   // n direction
    const int ty = tid / 16;   // m direction

    // Transposed-tile load mapping (A always; B when BT)
    const int aRow = tid / 4;          // 0..63 (+64)
    const int aCol = (tid % 4) * 4;    // 0,4,8,12
    // Direct-tile load mapping (B when !BT)
    const int bRow = tid / 32;         // 0..7 (+8)
    const int bCol = (tid % 32) * 4;   // 0..124

    float acc[8][8];
    #pragma unroll
    for (int i = 0; i < 8; i++)
        #pragma unroll
        for (int j = 0; j < 8; j++) acc[i][j] = 0.f;

    for (int k0 = 0; k0 < K; k0 += 16) {
        #pragma unroll
        for (int h = 0; h < 2; h++) {
            int r = aRow + h * 64;
            float4 v = *reinterpret_cast<const float4*>(
                &A[(long long)(m0 + r) * K + k0 + aCol]);
            As[aCol + 0][r] = v.x; As[aCol + 1][r] = v.y;
            As[aCol + 2][r] = v.z; As[aCol + 3][r] = v.w;
        }
        if (BT) {
            #pragma unroll
            for (int h = 0; h < 2; h++) {
                int r = aRow + h * 64;
                float4 v = *reinterpret_cast<const float4*>(
                    &B[(long long)(n0 + r) * K + k0 + aCol]);
                Bs[aCol + 0][r] = v.x; Bs[aCol + 1][r] = v.y;
                Bs[aCol + 2][r] = v.z; Bs[aCol + 3][r] = v.w;
            }
        } else {
            #pragma unroll
            for (int h = 0; h < 2; h++) {
                int r = bRow + h * 8;
                float4 v = *reinterpret_cast<const float4*>(
                    &B[(long long)(k0 + r) * N + n0 + bCol]);
                *reinterpret_cast<float4*>(&Bs[r][bCol]) = v;
            }
        }
        __syncthreads();

        #pragma unroll
        for (int kk = 0; kk < 16; kk++) {
            float ra[8], rb[8];
            #pragma unroll
            for (int i = 0; i < 8; i++) ra[i] = As[kk][ty * 8 + i];
            #pragma unroll
            for (int j = 0; j < 8; j++) rb[j] = Bs[kk][tx * 8 + j];
            #pragma unroll
            for (int i = 0; i < 8; i++)
                #pragma unroll
                for (int j = 0; j < 8; j++) acc[i][j] += ra[i] * rb[j];
        }
        __syncthreads();
    }

    #pragma unroll
    for (int i = 0; i < 8; i++) {
        int m = m0 + ty * 8 + i;
        #pragma unroll
        for (int j = 0; j < 8; j += 4) {
            int n = n0 + tx * 8 + j;
            float4 v;
            v.x = acc[i][j];     v.y = acc[i][j + 1];
            v.z = acc[i][j + 2]; v.w = acc[i][j + 3];
            if (HASBIAS) {
                v.x += bias[n];     v.y += bias[n + 1];
                v.z += bias[n + 2]; v.w += bias[n + 3];
            }
            *reinterpret_cast<float4*>(&C[(long long)m * N + n]) = v;
        }
    }
}

// ---------------------------------------------------------------------------
// softmax(sim * inv_sqrt) row-wise, threshold against l[b], write mask (0/1)
// One block (256 threads) per row of 1024.
// ---------------------------------------------------------------------------
__global__ void softmax_mask_kernel(const float* __restrict__ sim,
                                    float* __restrict__ mask) {
    const int row = blockIdx.x;       // b*M + m
    const int b = row >> 10;
    const float inv = 0.03125f;       // 1/sqrt(1024)
    __shared__ float srow[NDIM];
    __shared__ float red[256];
    const float* p = sim + (long long)row * NDIM;

    float lm = -1e30f;
    for (int j = threadIdx.x; j < NDIM; j += 256) {
        float v = p[j] * inv;
        srow[j] = v;
        lm = fmaxf(lm, v);
    }
    red[threadIdx.x] = lm;
    __syncthreads();
    for (int s = 128; s > 0; s >>= 1) {
        if (threadIdx.x < s) red[threadIdx.x] = fmaxf(red[threadIdx.x], red[threadIdx.x + s]);
        __syncthreads();
    }
    float mx = red[0];
    __syncthreads();

    float ls = 0.f;
    for (int j = threadIdx.x; j < NDIM; j += 256) ls += expf(srow[j] - mx);
    red[threadIdx.x] = ls;
    __syncthreads();
    for (int s = 128; s > 0; s >>= 1) {
        if (threadIdx.x < s) red[threadIdx.x] += red[threadIdx.x + s];
        __syncthreads();
    }
    float sum = red[0];
    float thr = g_l[b] * sum;   // S >= l  <=>  exp(x-mx) >= l*sum

    float* mrow = mask + (long long)row * NDIM;
    for (int j = threadIdx.x; j < NDIM; j += 256)
        mrow[j] = (expf(srow[j] - mx) >= thr) ? 1.f : 0.f;
}

// ---------------------------------------------------------------------------
// Masked softmax in place: p = softmax(where(mask, p*inv, -1e9)) per row.
// TRANS=false: mask[b][i][j]; TRANS=true: mask[b][j][i] (transposed mask).
// ---------------------------------------------------------------------------
template <bool TRANS>
__global__ void masked_softmax_kernel(float* __restrict__ scores,
                                      const float* __restrict__ mask) {
    const int row = blockIdx.x;    // b*1024 + i
    const int b = row >> 10;
    const int i = row & 1023;
    const float inv = 0.03125f;
    __shared__ float srow[NDIM];
    __shared__ float red[256];
    float* p = scores + (long long)row * NDIM;
    const float* mbase = mask + (long long)b * MDIM * NDIM;

    float lm = -1e30f;
    for (int j = threadIdx.x; j < NDIM; j += 256) {
        float mval = TRANS ? mbase[(long long)j * NDIM + i]
                           : mbase[(long long)i * NDIM + j];
        float v = (mval != 0.f) ? p[j] * inv : NEGINF;
        srow[j] = v;
        lm = fmaxf(lm, v);
    }
    red[threadIdx.x] = lm;
    __syncthreads();
    for (int s = 128; s > 0; s >>= 1) {
        if (threadIdx.x < s) red[threadIdx.x] = fmaxf(red[threadIdx.x], red[threadIdx.x + s]);
        __syncthreads();
    }
    float mx = red[0];
    __syncthreads();

    float ls = 0.f;
    for (int j = threadIdx.x; j < NDIM; j += 256) ls += expf(srow[j] - mx);
    red[threadIdx.x] = ls;
    __syncthreads();
    for (int s = 128; s > 0; s >>= 1) {
        if (threadIdx.x < s) red[threadIdx.x] += red[threadIdx.x + s];
        __syncthreads();
    }
    float rsum = 1.0f / red[0];

    for (int j = threadIdx.x; j < NDIM; j += 256)
        p[j] = expf(srow[j] - mx) * rsum;
}

// ---------------------------------------------------------------------------
// Launch
// ---------------------------------------------------------------------------
extern "C" void kernel_launch(void* const* d_in, const int* in_sizes, int n_in,
                              void* d_out, int out_size) {
    const float* oV     = (const float*)d_in[0];
    const float* oT     = (const float*)d_in[1];
    const float* Wq_v_w = (const float*)d_in[2];
    const float* Wq_v_b = (const float*)d_in[3];
    const float* Wk_t_w = (const float*)d_in[4];
    const float* Wk_t_b = (const float*)d_in[5];
    const float* Wv_t_w = (const float*)d_in[6];
    const float* Wv_t_b = (const float*)d_in[7];
    const float* Wq_t_w = (const float*)d_in[8];
    const float* Wq_t_b = (const float*)d_in[9];
    const float* Wk_v_w = (const float*)d_in[10];
    const float* Wk_v_b = (const float*)d_in[11];
    const float* Wv_v_w = (const float*)d_in[12];
    const float* Wv_v_b = (const float*)d_in[13];
    const float* ffn1_w = (const float*)d_in[14];
    const float* ffn1_b = (const float*)d_in[15];
    const float* ffn2_w = (const float*)d_in[16];
    const float* ffn2_b = (const float*)d_in[17];

    float* out = (float*)d_out;
    float* out_vt  = out;
    float* out_tv  = out + (long long)BSZ * MDIM * DTDIM;
    float* maskout = out + 2LL * BSZ * MDIM * DTDIM;

    float* scr = nullptr;
    cudaGetSymbolAddress((void**)&scr, g_scratch);
    float* s0 = scr;             // sim / scores
    float* s1 = scr + SLAB;      // Q
    float* s2 = scr + 2 * SLAB;  // K
    float* s3 = scr + 3 * SLAB;  // V

    const long long S = (long long)MDIM * NDIM;  // per-batch stride (all 1024x1024)
    dim3 ggrid(NDIM / 128, MDIM / 128, BSZ);

    // Phase 0: pooled FFN threshold
    pool_kernel<<<dim3(BSZ, 2), 256>>>(oV, oT);
    ffn_kernel<<<BSZ, HIDD>>>(ffn1_w, ffn1_b, ffn2_w, ffn2_b);

    // Phase 1: sim = oV @ oT^T, softmax+threshold -> mask
    gemm128<true, false><<<ggrid, 256>>>(oV, S, oT, S, s0, S, nullptr, MDIM, NDIM, DTDIM);
    softmax_mask_kernel<<<BSZ * MDIM, 256>>>(s0, maskout);

    // Phase 2: V -> T attention
    gemm128<true, true><<<ggrid, 256>>>(oV, S, Wq_v_w, 0, s1, S, Wq_v_b, MDIM, DTDIM, DTDIM);
    gemm128<true, true><<<ggrid, 256>>>(oT, S, Wk_t_w, 0, s2, S, Wk_t_b, NDIM, DTDIM, DTDIM);
    gemm128<true, true><<<ggrid, 256>>>(oT, S, Wv_t_w, 0, s3, S, Wv_t_b, NDIM, DTDIM, DTDIM);
    gemm128<true, false><<<ggrid, 256>>>(s1, S, s2, S, s0, S, nullptr, MDIM, NDIM, DTDIM);
    masked_softmax_kernel<false><<<BSZ * MDIM, 256>>>(s0, maskout);
    gemm128<false, false><<<ggrid, 256>>>(s0, S, s3, S, out_vt, S, nullptr, MDIM, DTDIM, NDIM);

    // Phase 3: T -> V attention (transposed mask)
    gemm128<true, true><<<ggrid, 256>>>(oT, S, Wq_t_w, 0, s1, S, Wq_t_b, NDIM, DTDIM, DTDIM);
    gemm128<true, true><<<ggrid, 256>>>(oV, S, Wk_v_w, 0, s2, S, Wk_v_b, MDIM, DTDIM, DTDIM);
    gemm128<true, true><<<ggrid, 256>>>(oV, S, Wv_v_w, 0, s3, S, Wv_v_b, MDIM, DTDIM, DTDIM);
    gemm128<true, false><<<ggrid, 256>>>(s1, S, s2, S, s0, S, nullptr, NDIM, MDIM, DTDIM);
    masked_softmax_kernel<true><<<BSZ * NDIM, 256>>>(s0, maskout);
    gemm128<false, false><<<ggrid, 256>>>(s0, S, s3, S, out_tv, S, nullptr, NDIM, DTDIM, MDIM);
}